// round 3
// baseline (speedup 1.0000x reference)
#include <cuda_runtime.h>

// Schroeder reverb: 4 series allpass + 4 parallel feedback combs (summed).
// T=131072 time steps, W=128 channels, fp32.
//
// Each lagged first-order recurrence y[n] = a*y[n-N] + u[n] decouples into N
// independent stride-N chains per channel. One thread per (residue, channel):
// the thread's x[n-N] / y[n-N] history lives entirely in registers, so each
// stage is a pure stream (1 read + 1 write per element). Allpass stages 2-4
// run in-place on a 64MB __device__ scratch buffer (fits in 126MB L2).
//
// R1 bug: in-place stages used a kernel whose in/out params were BOTH
// __restrict__ and got the same pointer -> compiler reordered the k=0
// zero-store before the k=0 history load (legal under restrict), corrupting
// every chain head. Fix: separate single-pointer in-place kernel, no restrict.
//
// Reference semantics (matches the jnp block-scan exactly):
//   allpass: y[k] = -g*y[k-1] + x[k] + g*x[k-1]  per chain, y[block 0] = 0
//   comb:    y[k] =  g*y[k-1] + x[k]             per chain, y[block 0] = 0

#define TT 131072
#define WW 128

__device__ float g_scratch[TT * WW];  // 64 MB static scratch (allowed; no cudaMalloc)

// Out-of-place allpass (stage 1: d_in -> scratch). in != out guaranteed.
__global__ void __launch_bounds__(WW) allpass_oop_kernel(
    const float* __restrict__ in, float* __restrict__ out, int N, float g)
{
    const int r = blockIdx.x;     // residue 0..N-1
    const int w = threadIdx.x;    // channel 0..127
    const int stride = N * WW;
    int idx = r * WW + w;

    float xprev = in[idx];        // k=0: x enters history, y forced to 0
    out[idx] = 0.0f;
    float yprev = 0.0f;

    const int kmax = (TT - 1 - r) / N;
#pragma unroll 4
    for (int k = 1; k <= kmax; k++) {
        idx += stride;
        float xk = in[idx];
        float y = fmaf(g, xprev - yprev, xk);   // y = x[k] + g*(x[k-1]-y[k-1])
        out[idx] = y;
        xprev = xk;
        yprev = y;
    }
}

// In-place allpass (stages 2-4 on scratch). Single pointer, NO restrict:
// the compiler must honor same-address load-before-store ordering.
__global__ void __launch_bounds__(WW) allpass_ip_kernel(
    float* buf, int N, float g)
{
    const int r = blockIdx.x;
    const int w = threadIdx.x;
    const int stride = N * WW;
    int idx = r * WW + w;

    float xprev = buf[idx];
    buf[idx] = 0.0f;
    float yprev = 0.0f;

    const int kmax = (TT - 1 - r) / N;
#pragma unroll 4
    for (int k = 1; k <= kmax; k++) {
        idx += stride;
        float xk = buf[idx];
        float y = fmaf(g, xprev - yprev, xk);
        buf[idx] = y;
        xprev = xk;
        yprev = y;
    }
}

template <bool ATOMIC>
__global__ void __launch_bounds__(WW) comb_kernel(
    const float* __restrict__ in, float* __restrict__ out, int N, float g)
{
    const int r = blockIdx.x;
    const int w = threadIdx.x;
    const int stride = N * WW;
    int idx = r * WW + w;

    if (!ATOMIC) out[idx] = 0.0f;   // first comb also clears the 0xAA poison
    float yprev = 0.0f;

    const int kmax = (TT - 1 - r) / N;
#pragma unroll 4
    for (int k = 1; k <= kmax; k++) {
        idx += stride;
        float xk = in[idx];
        float y = fmaf(g, yprev, xk);
        if (ATOMIC)
            atomicAdd(&out[idx], y);
        else
            out[idx] = y;
        yprev = y;
    }
}

extern "C" void kernel_launch(void* const* d_in, const int* in_sizes, int n_in,
                              void* d_out, int out_size)
{
    const float* x = (const float*)d_in[0];
    float* out = (float*)d_out;

    float* s;
    cudaGetSymbolAddress((void**)&s, g_scratch);

    // Series allpass chain. Stage 1 rewrites ALL of scratch from d_in each
    // call, so graph replays are deterministic.
    allpass_oop_kernel<<<225, WW>>>(x, s, 225, 0.7f);
    allpass_ip_kernel<<<556, WW>>>(s, 556, 0.7f);
    allpass_ip_kernel<<<441, WW>>>(s, 441, 0.7f);
    allpass_ip_kernel<<<341, WW>>>(s, 341, 0.7f);

    // Parallel comb bank, summed into d_out. Comb 1 covers every element
    // exactly once -> plain store. Combs 2-4 accumulate with atomics; each
    // address touched once per kernel, kernels serialize -> deterministic.
    comb_kernel<false><<<1116, WW>>>(s, out, 1116, 0.84f);
    comb_kernel<true><<<1188, WW>>>(s, out, 1188, 0.82f);
    comb_kernel<true><<<1277, WW>>>(s, out, 1277, 0.80f);
    comb_kernel<true><<<1356, WW>>>(s, out, 1356, 0.78f);
}

// round 6
// speedup vs baseline: 1.0964x; 1.0964x over previous
#include <cuda_runtime.h>

// Schroeder reverb: 4 series allpass + 4 parallel feedback combs, T=131072, W=128 fp32.
// (Resubmission of R4 kernel — previous round failed on broker infra, never ran.)
//
// Each lagged recurrence splits into N independent stride-N chains per channel.
// R3 profile showed pure concurrency starvation (DRAM 5.5%, issue 1.7%):
// too few threads, 4B loads. Fixes:
//   (a) float4 across channels (32 vec-lanes per time row) -> 4x bytes per LDG
//   (b) allpass chains segmented: payload P=128 steps per thread, preceded by
//       H=64 warm-up steps started from zero state. |a|<=0.7 => state error
//       decays as 0.7^64 ~ 1e-10: far below the 1e-3 threshold.
//       Segmentation requires out-of-place stages -> ping-pong scratch A/B.
//   (c) combs (N>=1116) have 142k+ chains already: unsegmented, float4,
//       same-thread vector RMW into d_out (serialized launches, deterministic).
//
// Chain semantics (matches the jnp block-scan):
//   allpass: y[k] = -g*y[k-1] + x[k] + g*x[k-1],  y[0] = 0 (x[0] enters history)
//   comb:    y[k] =  g*y[k-1] + x[k],             y[0] = 0

#define TT 131072
#define W4 32          // 128 channels = 32 float4
#define SEG_P 128      // payload chain-steps per segment thread
#define SEG_H 64       // warm-up steps (0.7^64 ~ 1e-10)

__device__ float4 g_scratchA[TT * W4];   // 64 MB
__device__ float4 g_scratchB[TT * W4];   // 64 MB

__device__ __forceinline__ float4 ap_step(float g, float4 xp, float4 yp, float4 xk) {
    float4 y;
    y.x = fmaf(g, xp.x - yp.x, xk.x);
    y.y = fmaf(g, xp.y - yp.y, xk.y);
    y.z = fmaf(g, xp.z - yp.z, xk.z);
    y.w = fmaf(g, xp.w - yp.w, xk.w);
    return y;
}

// Segmented allpass stage, out-of-place (in != out).
__global__ void __launch_bounds__(128) allpass_seg_kernel(
    const float4* __restrict__ in, float4* __restrict__ out,
    int N, int nseg, float g)
{
    const int tid = blockIdx.x * 128 + threadIdx.x;
    if (tid >= 32 * N * nseg) return;
    const int v   = tid & 31;          // float4 lane within the time row
    const int rn  = tid >> 5;
    const int r   = rn % N;            // residue (chain id within channel)
    const int seg = rn / N;            // segment along the chain

    const int len = (TT - 1 - r) / N + 1;   // chain length in k-steps
    const int kbp = seg * SEG_P;            // payload begin (k)
    if (kbp >= len) return;
    const int kend = min(len, kbp + SEG_P); // payload end (exclusive)
    const int kw = (kbp > SEG_H) ? (kbp - SEG_H) : 0;  // warm-up start

    const int stride = N * W4;
    float4 xprev, yprev = make_float4(0.f, 0.f, 0.f, 0.f);
    int k;
    if (kw == 0) {
        // exact chain head: y[0]=0, x[0] enters history
        const int idx0 = r * W4 + v;
        xprev = in[idx0];
        if (seg == 0) out[idx0] = make_float4(0.f, 0.f, 0.f, 0.f);
        k = 1;
    } else {
        // approximate restart: exact x history, zero y state (decays in warm-up)
        xprev = in[(kw - 1) * stride + r * W4 + v];
        k = kw;
    }

    int idx = k * stride + r * W4 + v;
    const int kp = (kbp > 1) ? kbp : 1;

    // warm-up: advance state, no stores
    for (; k < kp; ++k, idx += stride) {
        float4 xk = in[idx];
        yprev = ap_step(g, xprev, yprev, xk);
        xprev = xk;
    }
    // payload: compute + store
#pragma unroll 8
    for (; k < kend; ++k, idx += stride) {
        float4 xk = in[idx];
        float4 y = ap_step(g, xprev, yprev, xk);
        out[idx] = y;
        xprev = xk;
        yprev = y;
    }
}

// Feedback comb. MODE 0: plain store (first comb, covers every element, clears
// poison). MODE 1: same-thread vector read-modify-write accumulate.
template <int MODE>
__global__ void __launch_bounds__(128) comb_kernel(
    const float4* __restrict__ in, float4* __restrict__ out, int N, float g)
{
    const int tid = blockIdx.x * 128 + threadIdx.x;
    if (tid >= 32 * N) return;
    const int v = tid & 31;
    const int r = tid >> 5;

    const int len = (TT - 1 - r) / N + 1;
    const int stride = N * W4;
    int idx = r * W4 + v;

    if (MODE == 0) out[idx] = make_float4(0.f, 0.f, 0.f, 0.f);  // y[0] = 0
    float4 yprev = make_float4(0.f, 0.f, 0.f, 0.f);

#pragma unroll 8
    for (int k = 1; k < len; ++k) {
        idx += stride;
        float4 xk = in[idx];
        float4 y;
        y.x = fmaf(g, yprev.x, xk.x);
        y.y = fmaf(g, yprev.y, xk.y);
        y.z = fmaf(g, yprev.z, xk.z);
        y.w = fmaf(g, yprev.w, xk.w);
        if (MODE == 0) {
            out[idx] = y;
        } else {
            float4 o = out[idx];
            o.x += y.x; o.y += y.y; o.z += y.z; o.w += y.w;
            out[idx] = o;
        }
        yprev = y;
    }
}

static inline int ap_grid(int N, int nseg) { return (32 * N * nseg + 127) / 128; }
static inline int nseg_of(int N) {
    int maxlen = (TT - 1) / N + 1;
    return (maxlen + SEG_P - 1) / SEG_P;
}

extern "C" void kernel_launch(void* const* d_in, const int* in_sizes, int n_in,
                              void* d_out, int out_size)
{
    const float4* x = (const float4*)d_in[0];
    float4* out = (float4*)d_out;

    float4 *A, *B;
    cudaGetSymbolAddress((void**)&A, g_scratchA);
    cudaGetSymbolAddress((void**)&B, g_scratchB);

    // Series allpass chain, ping-pong out-of-place. Every stage fully
    // rewrites its destination -> graph replays are deterministic.
    { int N = 225, s = nseg_of(N); allpass_seg_kernel<<<ap_grid(N, s), 128>>>(x, A, N, s, 0.7f); }
    { int N = 556, s = nseg_of(N); allpass_seg_kernel<<<ap_grid(N, s), 128>>>(A, B, N, s, 0.7f); }
    { int N = 441, s = nseg_of(N); allpass_seg_kernel<<<ap_grid(N, s), 128>>>(B, A, N, s, 0.7f); }
    { int N = 341, s = nseg_of(N); allpass_seg_kernel<<<ap_grid(N, s), 128>>>(A, B, N, s, 0.7f); }

    // Parallel comb bank summed into d_out. Comb 1 covers every element once
    // (plain store); combs 2-4 accumulate via same-thread RMW, one kernel at a
    // time on the stream -> deterministic.
    comb_kernel<0><<<(32 * 1116 + 127) / 128, 128>>>(B, out, 1116, 0.84f);
    comb_kernel<1><<<(32 * 1188 + 127) / 128, 128>>>(B, out, 1188, 0.82f);
    comb_kernel<1><<<(32 * 1277 + 127) / 128, 128>>>(B, out, 1277, 0.80f);
    comb_kernel<1><<<(32 * 1356 + 127) / 128, 128>>>(B, out, 1356, 0.78f);
}

// round 7
// speedup vs baseline: 1.2558x; 1.1454x over previous
#include <cuda_runtime.h>

// Schroeder reverb: 4 series allpass + 4 parallel feedback combs, T=131072, W=128 fp32.
//
// R6 post-mortem: regs=40 proved ptxas collapsed the unroll-8 loop to MLP~2
// (1.4MB in flight -> 2.1TB/s). This version forces MLP=8 by explicitly
// batch-loading 8 float4s into registers before any recurrence step.
//
// Structure (unchanged from R6):
//  - float4 across channels (32 vec-lanes per time row)
//  - allpass chains segmented: payload P=128 steps, warm-up H=64 from zero
//    state (0.7^64 ~ 1e-10 relative error, threshold is 1e-3)
//  - ping-pong 64MB scratch buffers, all stages out-of-place
//  - combs unsegmented (chain len ~96-117), comb1 plain store, combs 2-4
//    same-thread vector RMW (serialized launches -> deterministic)
//
// Chain semantics (matches the jnp block-scan):
//   allpass: y[k] = -g*y[k-1] + x[k] + g*x[k-1],  y[0] = 0 (x[0] enters history)
//   comb:    y[k] =  g*y[k-1] + x[k],             y[0] = 0

#define TT 131072
#define W4 32
#define SEG_P 128
#define SEG_H 64
#define BATCH 8

__device__ float4 g_scratchA[TT * W4];   // 64 MB
__device__ float4 g_scratchB[TT * W4];   // 64 MB

__device__ __forceinline__ float4 ap_step(float g, float4 xp, float4 yp, float4 xk) {
    float4 y;
    y.x = fmaf(g, xp.x - yp.x, xk.x);
    y.y = fmaf(g, xp.y - yp.y, xk.y);
    y.z = fmaf(g, xp.z - yp.z, xk.z);
    y.w = fmaf(g, xp.w - yp.w, xk.w);
    return y;
}

// Segmented allpass stage, out-of-place (in != out).
__global__ void __launch_bounds__(128) allpass_seg_kernel(
    const float4* __restrict__ in, float4* __restrict__ out,
    int N, int nseg, float g)
{
    const int tid = blockIdx.x * 128 + threadIdx.x;
    if (tid >= 32 * N * nseg) return;
    const int v   = tid & 31;
    const int rn  = tid >> 5;
    const int r   = rn % N;
    const int seg = rn / N;

    const int len = (TT - 1 - r) / N + 1;
    const int kbp = seg * SEG_P;
    if (kbp >= len) return;
    const int kend = min(len, kbp + SEG_P);
    const int kw = (kbp > SEG_H) ? (kbp - SEG_H) : 0;

    const int stride = N * W4;
    float4 xprev, yprev = make_float4(0.f, 0.f, 0.f, 0.f);
    int k;
    if (kw == 0) {
        const int idx0 = r * W4 + v;
        xprev = in[idx0];                       // k=0: x enters history, y=0
        if (seg == 0) out[idx0] = make_float4(0.f, 0.f, 0.f, 0.f);
        k = 1;
    } else {
        xprev = in[(kw - 1) * stride + r * W4 + v];
        k = kw;
    }

    int idx = k * stride + r * W4 + v;
    const int kp = (kbp > 1) ? kbp : 1;

    // ---- warm-up: state only, no stores; batched loads force MLP=8 ----
    while (k + BATCH <= kp) {
        float4 xs[BATCH];
#pragma unroll
        for (int j = 0; j < BATCH; j++) xs[j] = in[idx + j * stride];
#pragma unroll
        for (int j = 0; j < BATCH; j++) {
            yprev = ap_step(g, xprev, yprev, xs[j]);
            xprev = xs[j];
        }
        idx += BATCH * stride;
        k += BATCH;
    }
    for (; k < kp; ++k, idx += stride) {
        float4 xk = in[idx];
        yprev = ap_step(g, xprev, yprev, xk);
        xprev = xk;
    }

    // ---- payload: batched load, then 8 steps + stores ----
    while (k + BATCH <= kend) {
        float4 xs[BATCH];
#pragma unroll
        for (int j = 0; j < BATCH; j++) xs[j] = in[idx + j * stride];
#pragma unroll
        for (int j = 0; j < BATCH; j++) {
            float4 y = ap_step(g, xprev, yprev, xs[j]);
            out[idx + j * stride] = y;
            xprev = xs[j];
            yprev = y;
        }
        idx += BATCH * stride;
        k += BATCH;
    }
    for (; k < kend; ++k, idx += stride) {
        float4 xk = in[idx];
        float4 y = ap_step(g, xprev, yprev, xk);
        out[idx] = y;
        xprev = xk;
        yprev = y;
    }
}

// Feedback comb. MODE 0: plain store. MODE 1: same-thread vector RMW accumulate.
template <int MODE>
__global__ void __launch_bounds__(128) comb_kernel(
    const float4* __restrict__ in, float4* __restrict__ out, int N, float g)
{
    const int tid = blockIdx.x * 128 + threadIdx.x;
    if (tid >= 32 * N) return;
    const int v = tid & 31;
    const int r = tid >> 5;

    const int len = (TT - 1 - r) / N + 1;
    const int stride = N * W4;
    int idx = r * W4 + v;

    if (MODE == 0) out[idx] = make_float4(0.f, 0.f, 0.f, 0.f);  // y[0] = 0
    float4 yprev = make_float4(0.f, 0.f, 0.f, 0.f);

    int k = 1;
    idx += stride;
    while (k + BATCH <= len) {
        float4 xs[BATCH];
#pragma unroll
        for (int j = 0; j < BATCH; j++) xs[j] = in[idx + j * stride];
        float4 os[BATCH];
        if (MODE == 1) {
#pragma unroll
            for (int j = 0; j < BATCH; j++) os[j] = out[idx + j * stride];
        }
#pragma unroll
        for (int j = 0; j < BATCH; j++) {
            float4 y;
            y.x = fmaf(g, yprev.x, xs[j].x);
            y.y = fmaf(g, yprev.y, xs[j].y);
            y.z = fmaf(g, yprev.z, xs[j].z);
            y.w = fmaf(g, yprev.w, xs[j].w);
            if (MODE == 0) {
                out[idx + j * stride] = y;
            } else {
                float4 o = os[j];
                o.x += y.x; o.y += y.y; o.z += y.z; o.w += y.w;
                out[idx + j * stride] = o;
            }
            yprev = y;
        }
        idx += BATCH * stride;
        k += BATCH;
    }
    for (; k < len; ++k, idx += stride) {
        float4 xk = in[idx];
        float4 y;
        y.x = fmaf(g, yprev.x, xk.x);
        y.y = fmaf(g, yprev.y, xk.y);
        y.z = fmaf(g, yprev.z, xk.z);
        y.w = fmaf(g, yprev.w, xk.w);
        if (MODE == 0) {
            out[idx] = y;
        } else {
            float4 o = out[idx];
            o.x += y.x; o.y += y.y; o.z += y.z; o.w += y.w;
            out[idx] = o;
        }
        yprev = y;
    }
}

static inline int ap_grid(int N, int nseg) { return (32 * N * nseg + 127) / 128; }
static inline int nseg_of(int N) {
    int maxlen = (TT - 1) / N + 1;
    return (maxlen + SEG_P - 1) / SEG_P;
}

extern "C" void kernel_launch(void* const* d_in, const int* in_sizes, int n_in,
                              void* d_out, int out_size)
{
    const float4* x = (const float4*)d_in[0];
    float4* out = (float4*)d_out;

    float4 *A, *B;
    cudaGetSymbolAddress((void**)&A, g_scratchA);
    cudaGetSymbolAddress((void**)&B, g_scratchB);

    // Series allpass chain, ping-pong out-of-place; every stage fully rewrites
    // its destination -> graph replays deterministic.
    { int N = 225, s = nseg_of(N); allpass_seg_kernel<<<ap_grid(N, s), 128>>>(x, A, N, s, 0.7f); }
    { int N = 556, s = nseg_of(N); allpass_seg_kernel<<<ap_grid(N, s), 128>>>(A, B, N, s, 0.7f); }
    { int N = 441, s = nseg_of(N); allpass_seg_kernel<<<ap_grid(N, s), 128>>>(B, A, N, s, 0.7f); }
    { int N = 341, s = nseg_of(N); allpass_seg_kernel<<<ap_grid(N, s), 128>>>(A, B, N, s, 0.7f); }

    // Parallel comb bank summed into d_out.
    comb_kernel<0><<<(32 * 1116 + 127) / 128, 128>>>(B, out, 1116, 0.84f);
    comb_kernel<1><<<(32 * 1188 + 127) / 128, 128>>>(B, out, 1188, 0.82f);
    comb_kernel<1><<<(32 * 1277 + 127) / 128, 128>>>(B, out, 1277, 0.80f);
    comb_kernel<1><<<(32 * 1356 + 127) / 128, 128>>>(B, out, 1356, 0.78f);
}

// round 8
// speedup vs baseline: 1.7809x; 1.4181x over previous
#include <cuda_runtime.h>

// Schroeder reverb: 4 series allpass + 4 parallel feedback combs, T=131072, W=128 fp32.
//
// R7 post-mortem: ptxas re-serialized the explicit batch loads (regs stayed 40,
// MLP~2). Robust fix = concurrency from THREADS, not per-thread MLP:
//   - allpass segments shrunk to P=64 (H=64 warm-up, 0.7^64 ~ 1e-10 error)
//     -> ~72k threads/stage (was 43k max)
//   - combs segmented too (len<=118, nseg=2; seg-1 warm-up spans the whole
//     prefix so combs remain bit-exact) -> 71-87k threads each
//   - loads issued via inline-PTX ld.global.nc.v4 to pin 8-wide batching
//
// Chain semantics (matches the jnp block-scan):
//   allpass: y[k] = -g*y[k-1] + x[k] + g*x[k-1],  y[0] = 0 (x[0] enters history)
//   comb:    y[k] =  g*y[k-1] + x[k],             y[0] = 0

#define TT 131072
#define W4 32
#define SEG_P 64
#define SEG_H 64
#define BATCH 8

__device__ float4 g_scratchA[TT * W4];   // 64 MB
__device__ float4 g_scratchB[TT * W4];   // 64 MB

__device__ __forceinline__ float4 ldg_nc4(const float4* p) {
    float4 v;
    asm volatile("ld.global.nc.v4.f32 {%0,%1,%2,%3}, [%4];"
                 : "=f"(v.x), "=f"(v.y), "=f"(v.z), "=f"(v.w)
                 : "l"(p));
    return v;
}

__device__ __forceinline__ float4 ap_step(float g, float4 xp, float4 yp, float4 xk) {
    float4 y;
    y.x = fmaf(g, xp.x - yp.x, xk.x);
    y.y = fmaf(g, xp.y - yp.y, xk.y);
    y.z = fmaf(g, xp.z - yp.z, xk.z);
    y.w = fmaf(g, xp.w - yp.w, xk.w);
    return y;
}

// Segmented allpass stage, out-of-place (in != out guaranteed).
__global__ void __launch_bounds__(128) allpass_seg_kernel(
    const float4* __restrict__ in, float4* __restrict__ out,
    int N, int nseg, float g)
{
    const int tid = blockIdx.x * 128 + threadIdx.x;
    if (tid >= 32 * N * nseg) return;
    const int v   = tid & 31;
    const int rn  = tid >> 5;
    const int r   = rn % N;
    const int seg = rn / N;

    const int len = (TT - 1 - r) / N + 1;
    const int kbp = seg * SEG_P;            // payload begin
    if (kbp >= len) return;
    const int kend = min(len, kbp + SEG_P); // payload end (exclusive)
    const int kw = (kbp > SEG_H) ? (kbp - SEG_H) : 0;

    const int stride = N * W4;
    float4 xprev, yprev = make_float4(0.f, 0.f, 0.f, 0.f);
    int k;
    if (kw == 0) {
        const int idx0 = r * W4 + v;
        xprev = ldg_nc4(in + idx0);          // k=0: x enters history, y=0
        if (seg == 0) out[idx0] = make_float4(0.f, 0.f, 0.f, 0.f);
        k = 1;
    } else {
        xprev = ldg_nc4(in + (kw - 1) * stride + r * W4 + v);
        k = kw;
    }

    int idx = k * stride + r * W4 + v;
    const int kp = (kbp > 1) ? kbp : 1;

    // warm-up: state only, batched 8-wide loads
    while (k + BATCH <= kp) {
        float4 xs[BATCH];
#pragma unroll
        for (int j = 0; j < BATCH; j++) xs[j] = ldg_nc4(in + idx + j * stride);
#pragma unroll
        for (int j = 0; j < BATCH; j++) {
            yprev = ap_step(g, xprev, yprev, xs[j]);
            xprev = xs[j];
        }
        idx += BATCH * stride; k += BATCH;
    }
    for (; k < kp; ++k, idx += stride) {
        float4 xk = ldg_nc4(in + idx);
        yprev = ap_step(g, xprev, yprev, xk);
        xprev = xk;
    }

    // payload: batched loads, 8 steps + stores
    while (k + BATCH <= kend) {
        float4 xs[BATCH];
#pragma unroll
        for (int j = 0; j < BATCH; j++) xs[j] = ldg_nc4(in + idx + j * stride);
#pragma unroll
        for (int j = 0; j < BATCH; j++) {
            float4 y = ap_step(g, xprev, yprev, xs[j]);
            out[idx + j * stride] = y;
            xprev = xs[j];
            yprev = y;
        }
        idx += BATCH * stride; k += BATCH;
    }
    for (; k < kend; ++k, idx += stride) {
        float4 xk = ldg_nc4(in + idx);
        float4 y = ap_step(g, xprev, yprev, xk);
        out[idx] = y;
        xprev = xk;
        yprev = y;
    }
}

// Segmented feedback comb. Chain len <= 118, SEG_P=64 -> nseg=2 and the
// seg-1 warm-up (kbp=64 <= H) starts at k=0: results stay bit-exact.
// MODE 0: plain store (first comb; also clears 0xAA poison).
// MODE 1: same-thread vector RMW accumulate (kernels serialize -> deterministic).
template <int MODE>
__global__ void __launch_bounds__(128) comb_kernel(
    const float4* __restrict__ in, float4* out, int N, int nseg, float g)
{
    const int tid = blockIdx.x * 128 + threadIdx.x;
    if (tid >= 32 * N * nseg) return;
    const int v   = tid & 31;
    const int rn  = tid >> 5;
    const int r   = rn % N;
    const int seg = rn / N;

    const int len = (TT - 1 - r) / N + 1;
    const int kbp = seg * SEG_P;
    if (kbp >= len) return;
    const int kend = min(len, kbp + SEG_P);
    const int kw = (kbp > SEG_H) ? (kbp - SEG_H) : 0;  // ==0 for len<=128

    const int stride = N * W4;
    float4 yprev = make_float4(0.f, 0.f, 0.f, 0.f);
    int k = (kw == 0) ? 1 : kw;
    if (kw == 0 && seg == 0 && MODE == 0)
        out[r * W4 + v] = make_float4(0.f, 0.f, 0.f, 0.f);   // y[0] = 0

    int idx = k * stride + r * W4 + v;
    const int kp = (kbp > 1) ? kbp : 1;

    // warm-up: state only
    while (k + BATCH <= kp) {
        float4 xs[BATCH];
#pragma unroll
        for (int j = 0; j < BATCH; j++) xs[j] = ldg_nc4(in + idx + j * stride);
#pragma unroll
        for (int j = 0; j < BATCH; j++) {
            yprev.x = fmaf(g, yprev.x, xs[j].x);
            yprev.y = fmaf(g, yprev.y, xs[j].y);
            yprev.z = fmaf(g, yprev.z, xs[j].z);
            yprev.w = fmaf(g, yprev.w, xs[j].w);
        }
        idx += BATCH * stride; k += BATCH;
    }
    for (; k < kp; ++k, idx += stride) {
        float4 xk = ldg_nc4(in + idx);
        yprev.x = fmaf(g, yprev.x, xk.x);
        yprev.y = fmaf(g, yprev.y, xk.y);
        yprev.z = fmaf(g, yprev.z, xk.z);
        yprev.w = fmaf(g, yprev.w, xk.w);
    }

    // payload
    while (k + BATCH <= kend) {
        float4 xs[BATCH];
#pragma unroll
        for (int j = 0; j < BATCH; j++) xs[j] = ldg_nc4(in + idx + j * stride);
        float4 os[BATCH];
        if (MODE == 1) {
#pragma unroll
            for (int j = 0; j < BATCH; j++) os[j] = out[idx + j * stride];
        }
#pragma unroll
        for (int j = 0; j < BATCH; j++) {
            float4 y;
            y.x = fmaf(g, yprev.x, xs[j].x);
            y.y = fmaf(g, yprev.y, xs[j].y);
            y.z = fmaf(g, yprev.z, xs[j].z);
            y.w = fmaf(g, yprev.w, xs[j].w);
            if (MODE == 0) {
                out[idx + j * stride] = y;
            } else {
                float4 o = os[j];
                o.x += y.x; o.y += y.y; o.z += y.z; o.w += y.w;
                out[idx + j * stride] = o;
            }
            yprev = y;
        }
        idx += BATCH * stride; k += BATCH;
    }
    for (; k < kend; ++k, idx += stride) {
        float4 xk = ldg_nc4(in + idx);
        float4 y;
        y.x = fmaf(g, yprev.x, xk.x);
        y.y = fmaf(g, yprev.y, xk.y);
        y.z = fmaf(g, yprev.z, xk.z);
        y.w = fmaf(g, yprev.w, xk.w);
        if (MODE == 0) {
            out[idx] = y;
        } else {
            float4 o = out[idx];
            o.x += y.x; o.y += y.y; o.z += y.z; o.w += y.w;
            out[idx] = o;
        }
        yprev = y;
    }
}

static inline int grid_of(int N, int nseg) { return (32 * N * nseg + 127) / 128; }
static inline int nseg_of(int N) {
    int maxlen = (TT - 1) / N + 1;
    return (maxlen + SEG_P - 1) / SEG_P;
}

extern "C" void kernel_launch(void* const* d_in, const int* in_sizes, int n_in,
                              void* d_out, int out_size)
{
    const float4* x = (const float4*)d_in[0];
    float4* out = (float4*)d_out;

    float4 *A, *B;
    cudaGetSymbolAddress((void**)&A, g_scratchA);
    cudaGetSymbolAddress((void**)&B, g_scratchB);

    // Series allpass chain, ping-pong out-of-place; every stage fully rewrites
    // its destination -> graph replays deterministic.
    { int N = 225, s = nseg_of(N); allpass_seg_kernel<<<grid_of(N, s), 128>>>(x, A, N, s, 0.7f); }
    { int N = 556, s = nseg_of(N); allpass_seg_kernel<<<grid_of(N, s), 128>>>(A, B, N, s, 0.7f); }
    { int N = 441, s = nseg_of(N); allpass_seg_kernel<<<grid_of(N, s), 128>>>(B, A, N, s, 0.7f); }
    { int N = 341, s = nseg_of(N); allpass_seg_kernel<<<grid_of(N, s), 128>>>(A, B, N, s, 0.7f); }

    // Parallel comb bank summed into d_out.
    { int N = 1116, s = nseg_of(N); comb_kernel<0><<<grid_of(N, s), 128>>>(B, out, N, s, 0.84f); }
    { int N = 1188, s = nseg_of(N); comb_kernel<1><<<grid_of(N, s), 128>>>(B, out, N, s, 0.82f); }
    { int N = 1277, s = nseg_of(N); comb_kernel<1><<<grid_of(N, s), 128>>>(B, out, N, s, 0.80f); }
    { int N = 1356, s = nseg_of(N); comb_kernel<1><<<grid_of(N, s), 128>>>(B, out, N, s, 0.78f); }
}

// round 9
// speedup vs baseline: 1.9904x; 1.1177x over previous
#include <cuda_runtime.h>

// Schroeder reverb: 4 series allpass + 4 parallel feedback combs, T=131072, W=128 fp32.
//
// Optimization history: R3 one-thread-per-chain was concurrency-starved
// (DRAM 5.5%). Thread count is the lever that works on this codegen (ptxas
// refuses >2 MLP per thread regardless of batching). R8: P=64 segments ->
// 72k threads/stage, DRAM 40%. R9 (this): allpass P=32/H=32 -> ~140k
// threads/stage. Restart error 0.7^32 ~ 1.1e-5, threshold 1e-3.
// Combs stay P=64 (exact: seg-1 warm-up spans the whole prefix).
//
// Chain semantics (matches the jnp block-scan):
//   allpass: y[k] = -g*y[k-1] + x[k] + g*x[k-1],  y[0] = 0 (x[0] enters history)
//   comb:    y[k] =  g*y[k-1] + x[k],             y[0] = 0

#define TT 131072
#define W4 32
#define AP_P 32        // allpass payload steps per segment
#define AP_H 32        // allpass warm-up steps (0.7^32 ~ 1.1e-5)
#define CB_P 64        // comb payload steps per segment
#define CB_H 64        // comb warm-up (covers full prefix -> bit-exact)
#define BATCH 8

__device__ float4 g_scratchA[TT * W4];   // 64 MB
__device__ float4 g_scratchB[TT * W4];   // 64 MB

__device__ __forceinline__ float4 ldg_nc4(const float4* p) {
    float4 v;
    asm volatile("ld.global.nc.v4.f32 {%0,%1,%2,%3}, [%4];"
                 : "=f"(v.x), "=f"(v.y), "=f"(v.z), "=f"(v.w)
                 : "l"(p));
    return v;
}

__device__ __forceinline__ float4 ap_step(float g, float4 xp, float4 yp, float4 xk) {
    float4 y;
    y.x = fmaf(g, xp.x - yp.x, xk.x);
    y.y = fmaf(g, xp.y - yp.y, xk.y);
    y.z = fmaf(g, xp.z - yp.z, xk.z);
    y.w = fmaf(g, xp.w - yp.w, xk.w);
    return y;
}

// Segmented allpass stage, out-of-place (in != out guaranteed).
__global__ void __launch_bounds__(128) allpass_seg_kernel(
    const float4* __restrict__ in, float4* __restrict__ out,
    int N, int nseg, float g)
{
    const int tid = blockIdx.x * 128 + threadIdx.x;
    if (tid >= 32 * N * nseg) return;
    const int v   = tid & 31;
    const int rn  = tid >> 5;
    const int r   = rn % N;
    const int seg = rn / N;

    const int len = (TT - 1 - r) / N + 1;
    const int kbp = seg * AP_P;             // payload begin
    if (kbp >= len) return;
    const int kend = min(len, kbp + AP_P);  // payload end (exclusive)
    const int kw = (kbp > AP_H) ? (kbp - AP_H) : 0;

    const int stride = N * W4;
    float4 xprev, yprev = make_float4(0.f, 0.f, 0.f, 0.f);
    int k;
    if (kw == 0) {
        const int idx0 = r * W4 + v;
        xprev = ldg_nc4(in + idx0);          // k=0: x enters history, y=0
        if (seg == 0) out[idx0] = make_float4(0.f, 0.f, 0.f, 0.f);
        k = 1;
    } else {
        xprev = ldg_nc4(in + (kw - 1) * stride + r * W4 + v);
        k = kw;
    }

    int idx = k * stride + r * W4 + v;
    const int kp = (kbp > 1) ? kbp : 1;

    // warm-up: state only
    while (k + BATCH <= kp) {
        float4 xs[BATCH];
#pragma unroll
        for (int j = 0; j < BATCH; j++) xs[j] = ldg_nc4(in + idx + j * stride);
#pragma unroll
        for (int j = 0; j < BATCH; j++) {
            yprev = ap_step(g, xprev, yprev, xs[j]);
            xprev = xs[j];
        }
        idx += BATCH * stride; k += BATCH;
    }
    for (; k < kp; ++k, idx += stride) {
        float4 xk = ldg_nc4(in + idx);
        yprev = ap_step(g, xprev, yprev, xk);
        xprev = xk;
    }

    // payload: compute + store
    while (k + BATCH <= kend) {
        float4 xs[BATCH];
#pragma unroll
        for (int j = 0; j < BATCH; j++) xs[j] = ldg_nc4(in + idx + j * stride);
#pragma unroll
        for (int j = 0; j < BATCH; j++) {
            float4 y = ap_step(g, xprev, yprev, xs[j]);
            out[idx + j * stride] = y;
            xprev = xs[j];
            yprev = y;
        }
        idx += BATCH * stride; k += BATCH;
    }
    for (; k < kend; ++k, idx += stride) {
        float4 xk = ldg_nc4(in + idx);
        float4 y = ap_step(g, xprev, yprev, xk);
        out[idx] = y;
        xprev = xk;
        yprev = y;
    }
}

// Segmented feedback comb. Chain len <= 118, CB_P=64 -> nseg=2; seg-1
// warm-up (kbp=64 <= CB_H) starts at k=0 so results stay bit-exact.
// MODE 0: plain store (first comb; also clears 0xAA poison).
// MODE 1: same-thread vector RMW accumulate (kernels serialize -> deterministic).
template <int MODE>
__global__ void __launch_bounds__(128) comb_kernel(
    const float4* __restrict__ in, float4* out, int N, int nseg, float g)
{
    const int tid = blockIdx.x * 128 + threadIdx.x;
    if (tid >= 32 * N * nseg) return;
    const int v   = tid & 31;
    const int rn  = tid >> 5;
    const int r   = rn % N;
    const int seg = rn / N;

    const int len = (TT - 1 - r) / N + 1;
    const int kbp = seg * CB_P;
    if (kbp >= len) return;
    const int kend = min(len, kbp + CB_P);
    const int kw = (kbp > CB_H) ? (kbp - CB_H) : 0;   // ==0 here

    const int stride = N * W4;
    float4 yprev = make_float4(0.f, 0.f, 0.f, 0.f);
    int k = (kw == 0) ? 1 : kw;
    if (kw == 0 && seg == 0 && MODE == 0)
        out[r * W4 + v] = make_float4(0.f, 0.f, 0.f, 0.f);   // y[0] = 0

    int idx = k * stride + r * W4 + v;
    const int kp = (kbp > 1) ? kbp : 1;

    // warm-up: state only
    while (k + BATCH <= kp) {
        float4 xs[BATCH];
#pragma unroll
        for (int j = 0; j < BATCH; j++) xs[j] = ldg_nc4(in + idx + j * stride);
#pragma unroll
        for (int j = 0; j < BATCH; j++) {
            yprev.x = fmaf(g, yprev.x, xs[j].x);
            yprev.y = fmaf(g, yprev.y, xs[j].y);
            yprev.z = fmaf(g, yprev.z, xs[j].z);
            yprev.w = fmaf(g, yprev.w, xs[j].w);
        }
        idx += BATCH * stride; k += BATCH;
    }
    for (; k < kp; ++k, idx += stride) {
        float4 xk = ldg_nc4(in + idx);
        yprev.x = fmaf(g, yprev.x, xk.x);
        yprev.y = fmaf(g, yprev.y, xk.y);
        yprev.z = fmaf(g, yprev.z, xk.z);
        yprev.w = fmaf(g, yprev.w, xk.w);
    }

    // payload
    while (k + BATCH <= kend) {
        float4 xs[BATCH];
#pragma unroll
        for (int j = 0; j < BATCH; j++) xs[j] = ldg_nc4(in + idx + j * stride);
        float4 os[BATCH];
        if (MODE == 1) {
#pragma unroll
            for (int j = 0; j < BATCH; j++) os[j] = out[idx + j * stride];
        }
#pragma unroll
        for (int j = 0; j < BATCH; j++) {
            float4 y;
            y.x = fmaf(g, yprev.x, xs[j].x);
            y.y = fmaf(g, yprev.y, xs[j].y);
            y.z = fmaf(g, yprev.z, xs[j].z);
            y.w = fmaf(g, yprev.w, xs[j].w);
            if (MODE == 0) {
                out[idx + j * stride] = y;
            } else {
                float4 o = os[j];
                o.x += y.x; o.y += y.y; o.z += y.z; o.w += y.w;
                out[idx + j * stride] = o;
            }
            yprev = y;
        }
        idx += BATCH * stride; k += BATCH;
    }
    for (; k < kend; ++k, idx += stride) {
        float4 xk = ldg_nc4(in + idx);
        float4 y;
        y.x = fmaf(g, yprev.x, xk.x);
        y.y = fmaf(g, yprev.y, xk.y);
        y.z = fmaf(g, yprev.z, xk.z);
        y.w = fmaf(g, yprev.w, xk.w);
        if (MODE == 0) {
            out[idx] = y;
        } else {
            float4 o = out[idx];
            o.x += y.x; o.y += y.y; o.z += y.z; o.w += y.w;
            out[idx] = o;
        }
        yprev = y;
    }
}

static inline int grid_of(int N, int nseg) { return (32 * N * nseg + 127) / 128; }
static inline int nseg_ap(int N) { int L = (TT - 1) / N + 1; return (L + AP_P - 1) / AP_P; }
static inline int nseg_cb(int N) { int L = (TT - 1) / N + 1; return (L + CB_P - 1) / CB_P; }

extern "C" void kernel_launch(void* const* d_in, const int* in_sizes, int n_in,
                              void* d_out, int out_size)
{
    const float4* x = (const float4*)d_in[0];
    float4* out = (float4*)d_out;

    float4 *A, *B;
    cudaGetSymbolAddress((void**)&A, g_scratchA);
    cudaGetSymbolAddress((void**)&B, g_scratchB);

    // Series allpass chain, ping-pong out-of-place; every stage fully rewrites
    // its destination -> graph replays deterministic.
    { int N = 225, s = nseg_ap(N); allpass_seg_kernel<<<grid_of(N, s), 128>>>(x, A, N, s, 0.7f); }
    { int N = 556, s = nseg_ap(N); allpass_seg_kernel<<<grid_of(N, s), 128>>>(A, B, N, s, 0.7f); }
    { int N = 441, s = nseg_ap(N); allpass_seg_kernel<<<grid_of(N, s), 128>>>(B, A, N, s, 0.7f); }
    { int N = 341, s = nseg_ap(N); allpass_seg_kernel<<<grid_of(N, s), 128>>>(A, B, N, s, 0.7f); }

    // Parallel comb bank summed into d_out.
    { int N = 1116, s = nseg_cb(N); comb_kernel<0><<<grid_of(N, s), 128>>>(B, out, N, s, 0.84f); }
    { int N = 1188, s = nseg_cb(N); comb_kernel<1><<<grid_of(N, s), 128>>>(B, out, N, s, 0.82f); }
    { int N = 1277, s = nseg_cb(N); comb_kernel<1><<<grid_of(N, s), 128>>>(B, out, N, s, 0.80f); }
    { int N = 1356, s = nseg_cb(N); comb_kernel<1><<<grid_of(N, s), 128>>>(B, out, N, s, 0.78f); }
}